// round 2
// baseline (speedup 1.0000x reference)
#include <cuda_runtime.h>
#include <math.h>

#define RR       2336
#define CIN      4
#define COUT     16
#define NK       2
#define NTHREADS 512
#define NWARP    (NTHREADS / 32)
#define RPT      5          // ceil(2336 / 512)

// W repacked: [k][i][o/4][r] as float4 (covers o = og*4 .. og*4+3)
__device__ float4 g_Wt4[NK * CIN * 4 * RR];

__global__ void wtrans_kernel(const float* __restrict__ W) {
    int t = blockIdx.x * blockDim.x + threadIdx.x;
    const int total = NK * CIN * 4 * RR;          // dest float4 count
    if (t >= total) return;
    int r  = t % RR;
    int io = t / RR;            // k*16 + i*4 + og
    int k  = io >> 4;
    int i  = (io >> 2) & 3;
    int og = io & 3;
    const float4* src = (const float4*)W;         // [k][r][i][og] float4s
    g_Wt4[t] = src[((k * RR + r) * CIN + i) * 4 + og];
}

// -------- block reduction helpers --------

template <int N>
__device__ __forceinline__ void block_sum(float* v, float* red, int lane, int wid) {
#pragma unroll
    for (int n = 0; n < N; ++n) {
        float x = v[n];
#pragma unroll
        for (int off = 16; off > 0; off >>= 1)
            x += __shfl_xor_sync(0xffffffffu, x, off);
        v[n] = x;
    }
    __syncthreads();
    if (lane == 0) {
#pragma unroll
        for (int n = 0; n < N; ++n) red[wid * N + n] = v[n];
    }
    __syncthreads();
#pragma unroll
    for (int n = 0; n < N; ++n) {
        float t = 0.f;
#pragma unroll
        for (int w = 0; w < NWARP; ++w) t += red[w * N + n];
        v[n] = t;
    }
}

__device__ __forceinline__ float block_max(float x, float* red, int lane, int wid) {
#pragma unroll
    for (int off = 16; off > 0; off >>= 1)
        x = fmaxf(x, __shfl_xor_sync(0xffffffffu, x, off));
    __syncthreads();
    if (lane == 0) red[wid] = x;
    __syncthreads();
    float m = red[0];
#pragma unroll
    for (int w = 1; w < NWARP; ++w) m = fmaxf(m, red[w]);
    return m;
}

__device__ __forceinline__ void squash16(const float* s, float* v) {
    float n = 0.f;
#pragma unroll
    for (int o = 0; o < COUT; ++o) n = fmaf(s[o], s[o], n);
    float f = sqrtf(n) / (1.f + n);
#pragma unroll
    for (int o = 0; o < COUT; ++o) v[o] = s[o] * f;
}

// -------- main kernel: one block handles batches (2*bid, 2*bid+1) --------

__global__ __launch_bounds__(NTHREADS, 1)
void caps_kernel(const float* __restrict__ u, float* __restrict__ out) {
    extern __shared__ float sm[];
    float* uji_s = sm;                 // [COUT][RR]  (batch 1), conflict-free
    float* red   = sm + COUT * RR;     // [NWARP * 17]

    const int tid  = threadIdx.x;
    const int lane = tid & 31;
    const int wid  = tid >> 5;
    const int b0 = blockIdx.x * 2;
    const int b1 = b0 + 1;
    const float* u0p = u + (size_t)b0 * RR * CIN;
    const float* u1p = u + (size_t)b1 * RR * CIN;

    float cls0[NK], cls1[NK];

    for (int k = 0; k < NK; ++k) {
        const float4* Wt4 = g_Wt4 + k * (CIN * 4 * RR);

        // ---------- Phase A: stream W once, u_ji for batch0 -> regs, batch1 -> smem
        float uji_r[RPT][COUT];
#pragma unroll
        for (int j = 0; j < RPT; ++j)
#pragma unroll
            for (int o = 0; o < COUT; ++o) uji_r[j][o] = 0.f;

#pragma unroll
        for (int j = 0; j < RPT; ++j) {
            int r = tid + j * NTHREADS;
            if (r < RR) {
                float4 a0 = *(const float4*)(u0p + (size_t)r * CIN);
                float4 a1 = *(const float4*)(u1p + (size_t)r * CIN);
                float c0[CIN] = {a0.x, a0.y, a0.z, a0.w};
                float c1[CIN] = {a1.x, a1.y, a1.z, a1.w};
                float acc1[COUT];
#pragma unroll
                for (int o = 0; o < COUT; ++o) acc1[o] = 0.f;
#pragma unroll
                for (int i = 0; i < CIN; ++i) {
#pragma unroll
                    for (int og = 0; og < 4; ++og) {
                        float4 w = Wt4[(i * 4 + og) * RR + r];
                        uji_r[j][og * 4 + 0] = fmaf(c0[i], w.x, uji_r[j][og * 4 + 0]);
                        uji_r[j][og * 4 + 1] = fmaf(c0[i], w.y, uji_r[j][og * 4 + 1]);
                        uji_r[j][og * 4 + 2] = fmaf(c0[i], w.z, uji_r[j][og * 4 + 2]);
                        uji_r[j][og * 4 + 3] = fmaf(c0[i], w.w, uji_r[j][og * 4 + 3]);
                        acc1[og * 4 + 0] = fmaf(c1[i], w.x, acc1[og * 4 + 0]);
                        acc1[og * 4 + 1] = fmaf(c1[i], w.y, acc1[og * 4 + 1]);
                        acc1[og * 4 + 2] = fmaf(c1[i], w.z, acc1[og * 4 + 2]);
                        acc1[og * 4 + 3] = fmaf(c1[i], w.w, acc1[og * 4 + 3]);
                    }
                }
#pragma unroll
                for (int o = 0; o < COUT; ++o)
                    uji_s[o * RR + r] = acc1[o];
            }
        }

        // ---------- Routing batch 0 (register u_ji)
        {
            float s[COUT], v[COUT];
#pragma unroll
            for (int o = 0; o < COUT; ++o) {
                float t = 0.f;
#pragma unroll
                for (int j = 0; j < RPT; ++j) t += uji_r[j][o];
                s[o] = t;
            }
            block_sum<COUT>(s, red, lane, wid);   // also makes uji_s visible
#pragma unroll
            for (int o = 0; o < COUT; ++o) s[o] *= (1.f / RR);
            squash16(s, v);

            float blr[RPT];
            for (int it = 0; it < 2; ++it) {
                float mloc = -1e30f;
#pragma unroll
                for (int j = 0; j < RPT; ++j) {
                    int r = tid + j * NTHREADS;
                    if (r < RR) {
                        float d = 0.f;
#pragma unroll
                        for (int o = 0; o < COUT; ++o)
                            d = fmaf(uji_r[j][o], v[o], d);
                        float nb = (it == 0) ? d : (blr[j] + d);
                        blr[j] = nb;
                        mloc = fmaxf(mloc, nb);
                    }
                }
                float m = block_max(mloc, red, lane, wid);

                float acc[COUT + 1];
#pragma unroll
                for (int o = 0; o <= COUT; ++o) acc[o] = 0.f;
#pragma unroll
                for (int j = 0; j < RPT; ++j) {
                    int r = tid + j * NTHREADS;
                    if (r < RR) {
                        float w = __expf(blr[j] - m);
                        acc[COUT] += w;
#pragma unroll
                        for (int o = 0; o < COUT; ++o)
                            acc[o] = fmaf(w, uji_r[j][o], acc[o]);
                    }
                }
                block_sum<COUT + 1>(acc, red, lane, wid);
                float invZ = 1.f / acc[COUT];
#pragma unroll
                for (int o = 0; o < COUT; ++o) s[o] = acc[o] * invZ;
                squash16(s, v);
            }
            float n = 0.f;
#pragma unroll
            for (int o = 0; o < COUT; ++o) n = fmaf(v[o], v[o], n);
            cls0[k] = sqrtf(n);
        }

        // ---------- Routing batch 1 (smem u_ji; uji_r dead -> regs reused)
        {
            float s[COUT], v[COUT];
#pragma unroll
            for (int o = 0; o < COUT; ++o) s[o] = 0.f;
#pragma unroll
            for (int j = 0; j < RPT; ++j) {
                int r = tid + j * NTHREADS;
                if (r < RR) {
#pragma unroll
                    for (int o = 0; o < COUT; ++o)
                        s[o] += uji_s[o * RR + r];
                }
            }
            block_sum<COUT>(s, red, lane, wid);
#pragma unroll
            for (int o = 0; o < COUT; ++o) s[o] *= (1.f / RR);
            squash16(s, v);

            float blr[RPT];
            for (int it = 0; it < 2; ++it) {
                float mloc = -1e30f;
#pragma unroll
                for (int j = 0; j < RPT; ++j) {
                    int r = tid + j * NTHREADS;
                    if (r < RR) {
                        float d = 0.f;
#pragma unroll
                        for (int o = 0; o < COUT; ++o)
                            d = fmaf(uji_s[o * RR + r], v[o], d);
                        float nb = (it == 0) ? d : (blr[j] + d);
                        blr[j] = nb;
                        mloc = fmaxf(mloc, nb);
                    }
                }
                float m = block_max(mloc, red, lane, wid);

                float acc[COUT + 1];
#pragma unroll
                for (int o = 0; o <= COUT; ++o) acc[o] = 0.f;
#pragma unroll
                for (int j = 0; j < RPT; ++j) {
                    int r = tid + j * NTHREADS;
                    if (r < RR) {
                        float w = __expf(blr[j] - m);
                        acc[COUT] += w;
#pragma unroll
                        for (int o = 0; o < COUT; ++o)
                            acc[o] = fmaf(w, uji_s[o * RR + r], acc[o]);
                    }
                }
                block_sum<COUT + 1>(acc, red, lane, wid);
                float invZ = 1.f / acc[COUT];
#pragma unroll
                for (int o = 0; o < COUT; ++o) s[o] = acc[o] * invZ;
                squash16(s, v);
            }
            float n = 0.f;
#pragma unroll
            for (int o = 0; o < COUT; ++o) n = fmaf(v[o], v[o], n);
            cls1[k] = sqrtf(n);
        }
        __syncthreads();   // uji_s safe to overwrite next k
    }

    // ---------- final 2-way softmax per batch
    if (tid == 0) {
        {
            float m = fmaxf(cls0[0], cls0[1]);
            float e0 = __expf(cls0[0] - m), e1 = __expf(cls0[1] - m);
            float inv = 1.f / (e0 + e1);
            out[b0 * NK + 0] = e0 * inv;
            out[b0 * NK + 1] = e1 * inv;
        }
        {
            float m = fmaxf(cls1[0], cls1[1]);
            float e0 = __expf(cls1[0] - m), e1 = __expf(cls1[1] - m);
            float inv = 1.f / (e0 + e1);
            out[b1 * NK + 0] = e0 * inv;
            out[b1 * NK + 1] = e1 * inv;
        }
    }
}

extern "C" void kernel_launch(void* const* d_in, const int* in_sizes, int n_in,
                              void* d_out, int out_size) {
    const float* u = (const float*)d_in[0];   // [1024, 2336, 4]
    const float* W = (const float*)d_in[1];   // [2, 2336, 4, 16]
    float* out = (float*)d_out;               // [1024, 2]

    const int wtotal = NK * CIN * 4 * RR;     // dest float4 count
    wtrans_kernel<<<(wtotal + 255) / 256, 256>>>(W);

    const int smem_bytes = (COUT * RR + NWARP * 17 + 8) * sizeof(float);
    cudaFuncSetAttribute(caps_kernel,
                         cudaFuncAttributeMaxDynamicSharedMemorySize, smem_bytes);
    caps_kernel<<<512, NTHREADS, smem_bytes>>>(u, out);
}

// round 3
// speedup vs baseline: 1.3498x; 1.3498x over previous
#include <cuda_runtime.h>
#include <math.h>

#define RR       2336
#define CIN      4
#define COUT     16
#define NK       2
#define NTHREADS 256
#define NWARP    8
#define RPTF     9            // full j iterations (9*256 = 2304)
#define RPT      10
#define RPAD     20           // floats per smem row (bank-conflict-free float4)

// W repacked: [k][og][i][r] float4 (float4 covers o = og*4 .. og*4+3)
__device__ float4 g_Wt4[NK * 16 * RR];

__global__ void wtrans_kernel(const float* __restrict__ W) {
    int t = blockIdx.x * blockDim.x + threadIdx.x;
    if (t >= NK * 16 * RR) return;
    int r  = t % RR;
    int q  = t / RR;          // k*16 + og*4 + i
    int i  = q & 3;
    int og = (q >> 2) & 3;
    int k  = q >> 4;
    const float4* src = (const float4*)W;   // [(k,r,i)][og]
    g_Wt4[t] = src[((k * RR + r) * CIN + i) * 4 + og];
}

template <int N>
__device__ __forceinline__ void block_sum(float* v, float* red, int lane, int wid) {
#pragma unroll
    for (int n = 0; n < N; ++n) {
        float x = v[n];
#pragma unroll
        for (int off = 16; off > 0; off >>= 1)
            x += __shfl_xor_sync(0xffffffffu, x, off);
        v[n] = x;
    }
    __syncthreads();
    if (lane == 0) {
#pragma unroll
        for (int n = 0; n < N; ++n) red[wid * N + n] = v[n];
    }
    __syncthreads();
#pragma unroll
    for (int n = 0; n < N; ++n) {
        float t = 0.f;
#pragma unroll
        for (int w = 0; w < NWARP; ++w) t += red[w * N + n];
        v[n] = t;
    }
}

__device__ __forceinline__ void squash16(const float* s, float* v) {
    float n0 = 0.f, n1 = 0.f;
#pragma unroll
    for (int o = 0; o < 8; ++o) {
        n0 = fmaf(s[o], s[o], n0);
        n1 = fmaf(s[o + 8], s[o + 8], n1);
    }
    float n = n0 + n1;
    float f = sqrtf(n) / (1.f + n);
#pragma unroll
    for (int o = 0; o < COUT; ++o) v[o] = s[o] * f;
}

__device__ __forceinline__ float dot16(const float* a, const float* b) {
    float d0 = 0.f, d1 = 0.f, d2 = 0.f, d3 = 0.f;
#pragma unroll
    for (int o = 0; o < 4; ++o) {
        d0 = fmaf(a[o],      b[o],      d0);
        d1 = fmaf(a[o + 4],  b[o + 4],  d1);
        d2 = fmaf(a[o + 8],  b[o + 8],  d2);
        d3 = fmaf(a[o + 12], b[o + 12], d3);
    }
    return (d0 + d1) + (d2 + d3);
}

// one block handles batches (2*bid, 2*bid+1)
__global__ __launch_bounds__(NTHREADS, 1)
void caps_kernel(const float* __restrict__ u, float* __restrict__ out) {
    extern __shared__ float sm[];
    float*  uji_s = sm;                 // [RR][RPAD], thread-private rows
    float4* uji4  = (float4*)sm;        // row r, group g at slot r*5 + g
    float*  red   = sm + RR * RPAD;

    const int tid  = threadIdx.x;
    const int lane = tid & 31;
    const int wid  = tid >> 5;
    const int b0 = blockIdx.x * 2;
    const int b1 = b0 + 1;
    const float4* u0p = (const float4*)(u + (size_t)b0 * RR * CIN);
    const float4* u1p = (const float4*)(u + (size_t)b1 * RR * CIN);

    float cls0[NK], cls1[NK];

    for (int k = 0; k < NK; ++k) {
        const float4* Wt4 = g_Wt4 + k * 16 * RR;

        // ================= Phase A: stream W once =================
        // batch0 u_ji -> registers, batch1 u_ji -> smem (own rows)
        float uji0[RPT][COUT];

#define PHASE_A_ROUTE(JIDX, RVAL)                                              \
        {                                                                      \
            const int r_ = (RVAL);                                             \
            float4 a0 = u0p[r_];                                               \
            float4 a1 = u1p[r_];                                               \
            _Pragma("unroll")                                                  \
            for (int og = 0; og < 4; ++og) {                                   \
                float4 w0 = Wt4[(og * 4 + 0) * RR + r_];                       \
                float4 w1 = Wt4[(og * 4 + 1) * RR + r_];                       \
                float4 w2 = Wt4[(og * 4 + 2) * RR + r_];                       \
                float4 w3 = Wt4[(og * 4 + 3) * RR + r_];                       \
                uji0[JIDX][og*4+0] = fmaf(a0.x,w0.x, fmaf(a0.y,w1.x, fmaf(a0.z,w2.x, a0.w*w3.x))); \
                uji0[JIDX][og*4+1] = fmaf(a0.x,w0.y, fmaf(a0.y,w1.y, fmaf(a0.z,w2.y, a0.w*w3.y))); \
                uji0[JIDX][og*4+2] = fmaf(a0.x,w0.z, fmaf(a0.y,w1.z, fmaf(a0.z,w2.z, a0.w*w3.z))); \
                uji0[JIDX][og*4+3] = fmaf(a0.x,w0.w, fmaf(a0.y,w1.w, fmaf(a0.z,w2.w, a0.w*w3.w))); \
                float q0 = fmaf(a1.x,w0.x, fmaf(a1.y,w1.x, fmaf(a1.z,w2.x, a1.w*w3.x))); \
                float q1 = fmaf(a1.x,w0.y, fmaf(a1.y,w1.y, fmaf(a1.z,w2.y, a1.w*w3.y))); \
                float q2 = fmaf(a1.x,w0.z, fmaf(a1.y,w1.z, fmaf(a1.z,w2.z, a1.w*w3.z))); \
                float q3 = fmaf(a1.x,w0.w, fmaf(a1.y,w1.w, fmaf(a1.z,w2.w, a1.w*w3.w))); \
                uji4[r_ * 5 + og] = make_float4(q0, q1, q2, q3);               \
            }                                                                  \
        }

#pragma unroll
        for (int j = 0; j < RPTF; ++j)
            PHASE_A_ROUTE(j, tid + j * NTHREADS)
        if (tid < 32) {
            PHASE_A_ROUTE(RPTF, tid + RPTF * NTHREADS)
        } else {
#pragma unroll
            for (int o = 0; o < COUT; ++o) uji0[RPTF][o] = 0.f;
        }

        // ================= Routing: batch 0 (register u_ji) =================
        {
            float s[COUT], v[COUT];
#pragma unroll
            for (int o = 0; o < COUT; ++o) {
                float t = 0.f;
#pragma unroll
                for (int j = 0; j < RPT; ++j) t += uji0[j][o];  // tail rows are 0
                s[o] = t;
            }
            block_sum<COUT>(s, red, lane, wid);
#pragma unroll
            for (int o = 0; o < COUT; ++o) s[o] *= (1.f / RR);
            squash16(s, v);

            float blr[RPT];
            for (int it = 0; it < 2; ++it) {
                float acc[COUT + 1];
#pragma unroll
                for (int o = 0; o <= COUT; ++o) acc[o] = 0.f;
#pragma unroll
                for (int j = 0; j < RPTF; ++j) {
                    float d  = dot16(uji0[j], v);
                    float nb = (it == 0) ? d : (blr[j] + d);
                    blr[j] = nb;
                    float w = __expf(nb);
                    acc[COUT] += w;
#pragma unroll
                    for (int o = 0; o < COUT; ++o)
                        acc[o] = fmaf(w, uji0[j][o], acc[o]);
                }
                if (tid < 32) {
                    float d  = dot16(uji0[RPTF], v);
                    float nb = (it == 0) ? d : (blr[RPTF] + d);
                    blr[RPTF] = nb;
                    float w = __expf(nb);
                    acc[COUT] += w;
#pragma unroll
                    for (int o = 0; o < COUT; ++o)
                        acc[o] = fmaf(w, uji0[RPTF][o], acc[o]);
                }
                block_sum<COUT + 1>(acc, red, lane, wid);
                float invZ = 1.f / acc[COUT];
#pragma unroll
                for (int o = 0; o < COUT; ++o) s[o] = acc[o] * invZ;
                squash16(s, v);
            }
            cls0[k] = sqrtf(dot16(v, v));
        }

        // ================= Routing: batch 1 (smem u_ji, own rows) =================
        {
            float s[COUT], v[COUT];
#pragma unroll
            for (int o = 0; o < COUT; ++o) s[o] = 0.f;
#pragma unroll
            for (int j = 0; j < RPTF; ++j) {
                int r = tid + j * NTHREADS;
#pragma unroll
                for (int og = 0; og < 4; ++og) {
                    float4 t4 = uji4[r * 5 + og];
                    s[og*4+0] += t4.x; s[og*4+1] += t4.y;
                    s[og*4+2] += t4.z; s[og*4+3] += t4.w;
                }
            }
            if (tid < 32) {
                int r = tid + RPTF * NTHREADS;
#pragma unroll
                for (int og = 0; og < 4; ++og) {
                    float4 t4 = uji4[r * 5 + og];
                    s[og*4+0] += t4.x; s[og*4+1] += t4.y;
                    s[og*4+2] += t4.z; s[og*4+3] += t4.w;
                }
            }
            block_sum<COUT>(s, red, lane, wid);
#pragma unroll
            for (int o = 0; o < COUT; ++o) s[o] *= (1.f / RR);
            squash16(s, v);

            float blr[RPT];
            for (int it = 0; it < 2; ++it) {
                float acc[COUT + 1];
#pragma unroll
                for (int o = 0; o <= COUT; ++o) acc[o] = 0.f;
#pragma unroll
                for (int j = 0; j < RPTF; ++j) {
                    int r = tid + j * NTHREADS;
                    float q[COUT];
#pragma unroll
                    for (int og = 0; og < 4; ++og) {
                        float4 t4 = uji4[r * 5 + og];
                        q[og*4+0] = t4.x; q[og*4+1] = t4.y;
                        q[og*4+2] = t4.z; q[og*4+3] = t4.w;
                    }
                    float d  = dot16(q, v);
                    float nb = (it == 0) ? d : (blr[j] + d);
                    blr[j] = nb;
                    float w = __expf(nb);
                    acc[COUT] += w;
#pragma unroll
                    for (int o = 0; o < COUT; ++o)
                        acc[o] = fmaf(w, q[o], acc[o]);
                }
                if (tid < 32) {
                    int r = tid + RPTF * NTHREADS;
                    float q[COUT];
#pragma unroll
                    for (int og = 0; og < 4; ++og) {
                        float4 t4 = uji4[r * 5 + og];
                        q[og*4+0] = t4.x; q[og*4+1] = t4.y;
                        q[og*4+2] = t4.z; q[og*4+3] = t4.w;
                    }
                    float d  = dot16(q, v);
                    float nb = (it == 0) ? d : (blr[RPTF] + d);
                    blr[RPTF] = nb;
                    float w = __expf(nb);
                    acc[COUT] += w;
#pragma unroll
                    for (int o = 0; o < COUT; ++o)
                        acc[o] = fmaf(w, q[o], acc[o]);
                }
                block_sum<COUT + 1>(acc, red, lane, wid);
                float invZ = 1.f / acc[COUT];
#pragma unroll
                for (int o = 0; o < COUT; ++o) s[o] = acc[o] * invZ;
                squash16(s, v);
            }
            cls1[k] = sqrtf(dot16(v, v));
        }
        // uji_s rows are thread-private; block_sum syncs already ordered everything
    }

    // ---------------- final 2-way softmax per batch
    if (tid == 0) {
        float m0 = fmaxf(cls0[0], cls0[1]);
        float e00 = __expf(cls0[0] - m0), e01 = __expf(cls0[1] - m0);
        float i0 = 1.f / (e00 + e01);
        out[b0 * NK + 0] = e00 * i0;
        out[b0 * NK + 1] = e01 * i0;

        float m1 = fmaxf(cls1[0], cls1[1]);
        float e10 = __expf(cls1[0] - m1), e11 = __expf(cls1[1] - m1);
        float i1 = 1.f / (e10 + e11);
        out[b1 * NK + 0] = e10 * i1;
        out[b1 * NK + 1] = e11 * i1;
    }
}

extern "C" void kernel_launch(void* const* d_in, const int* in_sizes, int n_in,
                              void* d_out, int out_size) {
    const float* u = (const float*)d_in[0];   // [1024, 2336, 4]
    const float* W = (const float*)d_in[1];   // [2, 2336, 4, 16]
    float* out = (float*)d_out;               // [1024, 2]

    const int wtotal = NK * 16 * RR;
    wtrans_kernel<<<(wtotal + 255) / 256, 256>>>(W);

    const int smem_bytes = (RR * RPAD + NWARP * 17 + 24) * sizeof(float);
    cudaFuncSetAttribute(caps_kernel,
                         cudaFuncAttributeMaxDynamicSharedMemorySize, smem_bytes);
    caps_kernel<<<512, NTHREADS, smem_bytes>>>(u, out);
}